// round 11
// baseline (speedup 1.0000x reference)
#include <cuda_runtime.h>
#include <cuda_bf16.h>
#include <math.h>
#include <stdint.h>

#define NB 4096
#define FEATN 30

// ---------------- scratch (static device globals; no allocation) ----------------
__device__ float g_fvs[NB * FEATN];
__device__ float g_fvd[NB * FEATN];
__device__ float g_fps[NB * FEATN];
__device__ float g_fpd[NB * FEATN];
__device__ float g_y30[NB * FEATN];
// conv2 weight tiles, bf16 hi/lo, SW128-swizzled images: 10 tiles x 4096 B
__device__ __align__(16) unsigned char g_w2t[10 * 4096];

// ---------------- f32x2 helpers ----------------
typedef unsigned long long ull_t;
__device__ __forceinline__ ull_t f2pack(float lo, float hi) {
    ull_t r; asm("mov.b64 %0, {%1,%2};" : "=l"(r) : "f"(lo), "f"(hi)); return r;
}
__device__ __forceinline__ ull_t f2dup(float v) { return f2pack(v, v); }
__device__ __forceinline__ void f2fma(ull_t& d, ull_t a, ull_t b) {
    asm("fma.rn.f32x2 %0, %1, %2, %0;" : "+l"(d) : "l"(a), "l"(b));
}
__device__ __forceinline__ void f2unpack(ull_t v, float& lo, float& hi) {
    asm("mov.b64 {%0,%1}, %2;" : "=f"(lo), "=f"(hi) : "l"(v));
}

// ---------------- warp-MMA helpers (sm_80-path, legal on compute_103) ----------
__device__ __forceinline__ uint32_t smem_u32(const void* p) {
    uint32_t a;
    asm("{ .reg .u64 t; cvta.to.shared.u64 t, %1; cvt.u32.u64 %0, t; }" : "=r"(a) : "l"(p));
    return a;
}
__device__ __forceinline__ uint32_t sw128(uint32_t o) { return o ^ ((o >> 3) & 0x70); }

__device__ __forceinline__ void ldmx4(uint32_t* r, uint32_t addr) {
    asm volatile("ldmatrix.sync.aligned.m8n8.x4.shared.b16 {%0,%1,%2,%3}, [%4];"
                 : "=r"(r[0]), "=r"(r[1]), "=r"(r[2]), "=r"(r[3]) : "r"(addr));
}
__device__ __forceinline__ void ldmx2(uint32_t* r, uint32_t addr) {
    asm volatile("ldmatrix.sync.aligned.m8n8.x2.shared.b16 {%0,%1}, [%2];"
                 : "=r"(r[0]), "=r"(r[1]) : "r"(addr));
}
__device__ __forceinline__ void mma16816(float* d, const uint32_t* a, const uint32_t* b) {
    asm volatile("mma.sync.aligned.m16n8k16.row.col.f32.bf16.bf16.f32 "
                 "{%0,%1,%2,%3}, {%4,%5,%6,%7}, {%8,%9}, {%0,%1,%2,%3};"
                 : "+f"(d[0]), "+f"(d[1]), "+f"(d[2]), "+f"(d[3])
                 : "r"(a[0]), "r"(a[1]), "r"(a[2]), "r"(a[3]), "r"(b[0]), "r"(b[1]));
}

// =======================================================================
// Prep: build bf16 hi/lo SW128 tile images of conv2 weights.
// =======================================================================
__global__ void prep_w2t(const float* __restrict__ W2) {
    int i = blockIdx.x * 256 + threadIdx.x;       // 10*32*64 = 20480
    if (i < 20480) {
        int tile = i >> 11;
        int rem  = i & 2047;
        int n = rem >> 6, c = rem & 63;
        int half = tile / 5, k = tile % 5;
        float w = (n < 30) ? W2[n * 320 + c * 5 + k] : 0.f;
        __nv_bfloat16 wh = __float2bfloat16(w);
        __nv_bfloat16 val = half ? __float2bfloat16(w - __bfloat162float(wh)) : wh;
        *reinterpret_cast<__nv_bfloat16*>(
            g_w2t + tile * 4096 + sw128((uint32_t)(n * 128 + c * 2))) = val;
    }
}

// =======================================================================
// Encode kernel (MMA version): conv1d(3->64,K=3) as im2col GEMM (M=1024,
// N=64, K=16 padded from 9), bf16 hi/lo 3-product emulated fp32, ReLU +
// time-mean in MMA register accumulators, then two 64x30 heads.
// One block per sample, 512 threads: warps 0-7 = V modality, 8-15 = P.
// im2col rows: 48-byte stride (conflict-free for ldmatrix), col j = c*3+k.
// =======================================================================
#define EIM_STR   48u
#define EIM_SZ    49152u                 /* 1024 rows x 48 B */
#define EW_OFF    196608u                /* 4 x 2048 B: Vh, Vl, Ph, Pl */
#define EPART_OFF 204800u                /* 2 x 8 x 64 floats */
#define EBC_OFF   208896u                /* 2 x 64 floats */
#define EHSH_OFF  209408u                /* 2 x 64 floats */
#define ENC_SMEM  209920

__global__ __launch_bounds__(512) void encode_kernel(
    const float* __restrict__ S_V, const float* __restrict__ S_P,
    const float* __restrict__ Wc_v, const float* __restrict__ bc_v,
    const float* __restrict__ Ws_v, const float* __restrict__ bs_v,
    const float* __restrict__ Wd_v, const float* __restrict__ bd_v,
    const float* __restrict__ Wc_p, const float* __restrict__ bc_p,
    const float* __restrict__ Ws_p, const float* __restrict__ bs_p,
    const float* __restrict__ Wd_p, const float* __restrict__ bd_p)
{
    extern __shared__ __align__(16) unsigned char smraw[];
    const uint32_t smb = smem_u32(smraw);

    const int tid  = threadIdx.x;
    const int b    = blockIdx.x;
    const int half = tid >> 8;          // 0 = V, 1 = P
    const int htid = tid & 255;
    const int lane = tid & 31;
    const int hwid = (tid >> 5) & 7;    // warp within half

    const uint32_t imh_off = (uint32_t)half * (2u * EIM_SZ);
    const uint32_t iml_off = imh_off + EIM_SZ;
    const uint32_t wh_off  = EW_OFF + (uint32_t)half * 4096u;

    float* part = (float*)(smraw + EPART_OFF);
    float* bcs  = (float*)(smraw + EBC_OFF);
    float* hsh  = (float*)(smraw + EHSH_OFF);

    // ---- zero pad cols 9..15 (bytes 18..31) of im rows and W rows ----------
    for (int i = tid; i < 4352; i += 512) {
        uint32_t base;
        if (i < 4096) base = (uint32_t)(i >> 10) * EIM_SZ + (uint32_t)(i & 1023) * EIM_STR;
        else {
            int j = i - 4096;
            base = EW_OFF + (uint32_t)(j >> 6) * 2048u + (uint32_t)(j & 63) * 32u;
        }
        *reinterpret_cast<uint16_t*>(smraw + base + 18) = 0;
        *reinterpret_cast<uint32_t*>(smraw + base + 20) = 0;
        *reinterpret_cast<uint32_t*>(smraw + base + 24) = 0;
        *reinterpret_cast<uint32_t*>(smraw + base + 28) = 0;
    }

    // ---- fill im2col (hi/lo) from S: x[c][t] -> rows t-k, col c*3+k --------
    {
        const float* Sb = (half ? S_P : S_V) + (size_t)b * 3072;
        for (int i = htid; i < 3072; i += 256) {
            const int t = i / 3, c = i - t * 3;
            const float v = Sb[i];
            const __nv_bfloat16 vh = __float2bfloat16(v);
            const __nv_bfloat16 vl = __float2bfloat16(v - __bfloat162float(vh));
#pragma unroll
            for (int k = 0; k < 3; k++) {
                const int r = t - k;
                if (r >= 0 && r <= 1021) {
                    const uint32_t off = (uint32_t)r * EIM_STR + (uint32_t)(c * 3 + k) * 2;
                    *reinterpret_cast<__nv_bfloat16*>(smraw + imh_off + off) = vh;
                    *reinterpret_cast<__nv_bfloat16*>(smraw + iml_off + off) = vl;
                }
            }
        }
    }
    // ---- fill W tiles (hi/lo): row o, col j = c*3+k (matches Wc layout) ----
    {
        const float* Wc = half ? Wc_p : Wc_v;
        for (int i = htid; i < 576; i += 256) {
            const int o = i / 9, j = i - o * 9;
            const float w = Wc[i];
            const __nv_bfloat16 wh = __float2bfloat16(w);
            const __nv_bfloat16 wl = __float2bfloat16(w - __bfloat162float(wh));
            *reinterpret_cast<__nv_bfloat16*>(smraw + wh_off + o * 32 + j * 2) = wh;
            *reinterpret_cast<__nv_bfloat16*>(smraw + wh_off + 2048 + o * 32 + j * 2) = wl;
        }
        if (htid < 64) bcs[half * 64 + htid] = (half ? bc_p : bc_v)[htid];
    }
    __syncthreads();

    // ---- MMA phase: 8 m-tiles per warp, B fragments register-resident ------
    uint32_t bhf[8][2], blf[8][2];
    float bias0[8], bias1[8];
#pragma unroll
    for (int nt = 0; nt < 8; nt++) {
        const uint32_t baddr = smb + wh_off +
            (uint32_t)(nt * 8 + (lane & 7)) * 32 + (uint32_t)((lane >> 3) & 1) * 16;
        ldmx2(bhf[nt], baddr);
        ldmx2(blf[nt], baddr + 2048);
        const int o = nt * 8 + (lane & 3) * 2;
        bias0[nt] = bcs[half * 64 + o];
        bias1[nt] = bcs[half * 64 + o + 1];
    }

    float s0[8], s1[8];
#pragma unroll
    for (int nt = 0; nt < 8; nt++) { s0[nt] = 0.f; s1[nt] = 0.f; }

#pragma unroll
    for (int mt = 0; mt < 8; mt++) {
        const int R = (hwid * 8 + mt) * 16;
        const uint32_t ao = smb + imh_off +
            (uint32_t)(R + (lane & 15)) * EIM_STR + (uint32_t)(lane >> 4) * 16;
        uint32_t Ah[4], Al[4];
        ldmx4(Ah, ao);
        ldmx4(Al, ao + EIM_SZ);
        const bool r1ok = (R + 8 + (lane >> 2)) < 1022;   // row r0 always < 1022
#pragma unroll
        for (int nt = 0; nt < 8; nt++) {
            float d[4] = {0.f, 0.f, 0.f, 0.f};
            mma16816(d, Ah, bhf[nt]);
            mma16816(d, Al, bhf[nt]);
            mma16816(d, Ah, blf[nt]);
            s0[nt] += fmaxf(d[0] + bias0[nt], 0.f);
            s1[nt] += fmaxf(d[1] + bias1[nt], 0.f);
            if (r1ok) {
                s0[nt] += fmaxf(d[2] + bias0[nt], 0.f);
                s1[nt] += fmaxf(d[3] + bias1[nt], 0.f);
            }
        }
    }

    // ---- reduce over the 8 lanes sharing each column, write per-warp part --
#pragma unroll
    for (int nt = 0; nt < 8; nt++) {
#pragma unroll
        for (int off = 4; off <= 16; off <<= 1) {
            s0[nt] += __shfl_xor_sync(0xffffffffu, s0[nt], off);
            s1[nt] += __shfl_xor_sync(0xffffffffu, s1[nt], off);
        }
    }
    if (lane < 4) {
#pragma unroll
        for (int nt = 0; nt < 8; nt++) {
            const int o = nt * 8 + lane * 2;
            part[(half * 8 + hwid) * 64 + o]     = s0[nt];
            part[(half * 8 + hwid) * 64 + o + 1] = s1[nt];
        }
    }
    __syncthreads();

    if (htid < 64) {
        float s = 0.f;
#pragma unroll
        for (int w = 0; w < 8; w++) s += part[(half * 8 + w) * 64 + htid];
        hsh[half * 64 + htid] = s * (1.f / 1022.f);
    }
    __syncthreads();

    // ---- heads ------------------------------------------------------------
    if (htid < 60) {
        const int  j2 = htid % 30;
        const bool first = htid < 30;
        const float* Wm  = first ? (half ? Ws_p : Ws_v) : (half ? Wd_p : Wd_v);
        const float* bm  = first ? (half ? bs_p : bs_v) : (half ? bd_p : bd_v);
        float* outp = first ? (half ? g_fps : g_fvs) : (half ? g_fpd : g_fvd);
        const float* hv = hsh + half * 64;
        float s = bm[j2];
        for (int i = 0; i < 64; i++) s = fmaf(hv[i], Wm[i * 30 + j2], s);
        outp[b * 30 + j2] = s;
    }
}

// =======================================================================
// Physical-model kernel (unchanged from R10, 560us version).
// =======================================================================
#define XS_OFF      0u
#define WBUF_OFF    0u
#define CO_OFF      0u
#define P1H_OFF     40960u
#define P1L_OFF     73728u
#define PART_OFF    106496u
#define PHYS_SMEM   108416
#define COSTR       33

__global__ __launch_bounds__(512, 2) void phys_kernel(
    const float* __restrict__ S_P1,
    const float* __restrict__ W1, const float* __restrict__ b1,
    const float* __restrict__ b2)
{
    extern __shared__ __align__(16) unsigned char smraw[];
    const uint32_t smb = smem_u32(smraw);
    float* xs   = (float*)(smraw + XS_OFF);
    float* part = (float*)(smraw + PART_OFF);

    const int tid  = threadIdx.x;
    const int b    = blockIdx.x;
    const int wid  = tid >> 5;
    const int lane = tid & 31;

    const float* Sb = S_P1 + (size_t)b * 3072;
    for (int i = tid; i < 3072; i += 512) xs[(i % 3) * 1032 + i / 3] = Sb[i];
    __syncthreads();

    // -------- conv1 (K=5, C=3, O=64) + maxpool4, o-pair f32x2 ---------------
    {
        const int pg = tid >> 4;
        const int tg = tid & 15;
        const int o0 = pg * 2;
        ull_t WU[15];
#pragma unroll
        for (int i = 0; i < 15; i++)
            WU[i] = f2pack(W1[o0 * 15 + i], W1[o0 * 15 + 15 + i]);
        const ull_t Bp = f2pack(b1[o0], b1[o0 + 1]);

        for (int m = 0; m < 16; m++) {
            const int j = tg + m * 16;
            if (j < 255) {
                const int t0 = 4 * j;
                ull_t A[4] = {Bp, Bp, Bp, Bp};
#pragma unroll
                for (int c = 0; c < 3; c++) {
                    const float* xr = xs + c * 1032 + t0;
                    float4 qa = *(const float4*)xr;
                    float4 qb = *(const float4*)(xr + 4);
                    ull_t X[8];
                    X[0] = f2dup(qa.x); X[1] = f2dup(qa.y); X[2] = f2dup(qa.z);
                    X[3] = f2dup(qa.w); X[4] = f2dup(qb.x); X[5] = f2dup(qb.y);
                    X[6] = f2dup(qb.z); X[7] = f2dup(qb.w);
#pragma unroll
                    for (int k = 0; k < 5; k++) {
                        const ull_t W = WU[c * 5 + k];
#pragma unroll
                        for (int p = 0; p < 4; p++) f2fma(A[p], X[p + k], W);
                    }
                }
                float u[4], v[4];
#pragma unroll
                for (int p = 0; p < 4; p++) f2unpack(A[p], u[p], v[p]);
                const float pa = fmaxf(fmaxf(u[0], u[1]), fmaxf(u[2], u[3]));
                const float pb = fmaxf(fmaxf(v[0], v[1]), fmaxf(v[2], v[3]));
                __nv_bfloat16 h0 = __float2bfloat16(pa);
                __nv_bfloat16 h1 = __float2bfloat16(pb);
                __nv_bfloat16 l0 = __float2bfloat16(pa - __bfloat162float(h0));
                __nv_bfloat16 l1 = __float2bfloat16(pb - __bfloat162float(h1));
                const uint32_t off = sw128((uint32_t)(j * 128 + o0 * 2));
                *reinterpret_cast<__nv_bfloat162*>(smraw + P1H_OFF + off) =
                    __halves2bfloat162(h0, h1);
                *reinterpret_cast<__nv_bfloat162*>(smraw + P1L_OFF + off) =
                    __halves2bfloat162(l0, l1);
            }
        }
    }
    if (tid < 32) {
        const uint32_t off = sw128((uint32_t)(255 * 128 + tid * 4));
        *reinterpret_cast<uint32_t*>(smraw + P1H_OFF + off) = 0u;
        *reinterpret_cast<uint32_t*>(smraw + P1L_OFF + off) = 0u;
    }
    __syncthreads();

    {
        const uint4* gw = (const uint4*)g_w2t;
        uint4* swp = (uint4*)(smraw + WBUF_OFF);
        for (int i = tid; i < 2560; i += 512) swp[i] = gw[i];
    }
    __syncthreads();

    // -------- conv2: shifts folded into A row base, register accumulation ----
    const uint32_t a_rowl = (uint32_t)(lane & 15);
    const uint32_t a_koff = (uint32_t)((lane >> 4) * 16);
    const uint32_t bn     = (uint32_t)(lane & 7) * 128;
    const uint32_t bkoff  = (uint32_t)((lane >> 3) & 1) * 16;

    float d[4][4];
#pragma unroll
    for (int nt = 0; nt < 4; nt++)
#pragma unroll
        for (int i = 0; i < 4; i++) d[nt][i] = 0.f;

#pragma unroll
    for (int k = 0; k < 5; k++) {
        const uint32_t bbase_h = smb + WBUF_OFF + (uint32_t)k * 4096;
        const uint32_t bbase_l = bbase_h + 5u * 4096;
        const uint32_t arow    = (uint32_t)(wid * 16 + k) + a_rowl;
#pragma unroll
        for (int ks = 0; ks < 4; ks++) {
            uint32_t Ah[4], Al[4];
            const uint32_t ao = sw128(arow * 128 + (uint32_t)ks * 32 + a_koff);
            ldmx4(Ah, smb + P1H_OFF + ao);
            ldmx4(Al, smb + P1L_OFF + ao);
#pragma unroll
            for (int nt = 0; nt < 4; nt++) {
                const uint32_t bo =
                    sw128(bn + (uint32_t)nt * 1024 + (uint32_t)ks * 32 + bkoff);
                uint32_t bh[2], bl[2];
                ldmx2(bh, bbase_h + bo);
                ldmx2(bl, bbase_l + bo);
                mma16816(d[nt], Ah, bh);
                mma16816(d[nt], Al, bh);
                mma16816(d[nt], Ah, bl);
            }
        }
    }
    __syncthreads();

    {
        float* conv_out = (float*)(smraw + CO_OFF);
        const int t0 = wid * 16 + (lane >> 2);
        const int t1 = t0 + 8;
        const int n0 = (lane & 3) * 2;
#pragma unroll
        for (int nt = 0; nt < 4; nt++) {
            const int n = nt * 8 + n0;
            if (t0 < 248) {
                conv_out[t0 * COSTR + n]     = d[nt][0];
                conv_out[t0 * COSTR + n + 1] = d[nt][1];
            }
            if (t1 < 248) {
                conv_out[t1 * COSTR + n]     = d[nt][2];
                conv_out[t1 * COSTR + n + 1] = d[nt][3];
            }
        }
    }
    __syncthreads();

    {
        float* conv_out = (float*)(smraw + CO_OFF);
        if (tid < 480) {
            const int n = tid >> 4, jg = tid & 15;
            float s = 0.f;
#pragma unroll
            for (int j = jg; j < 62; j += 16) {
                const float* cr = conv_out + 4 * j * COSTR + n;
                float mx = fmaxf(fmaxf(cr[0], cr[COSTR]),
                                 fmaxf(cr[2 * COSTR], cr[3 * COSTR]));
                s += mx;
            }
            part[n * 16 + jg] = s;
        }
    }
    __syncthreads();
    if (tid < 30) {
        float s = 0.f;
#pragma unroll
        for (int g = 0; g < 16; g++) s += part[tid * 16 + g];
        g_y30[b * 30 + tid] = s * (1.f / 62.f) + b2[tid];
    }
}

// =======================================================================
// Fusion kernel (unchanged).
// =======================================================================
__global__ __launch_bounds__(256) void fuse_kernel(
    const int* __restrict__ pairs,
    const float* __restrict__ Wsp, const float* __restrict__ bsp,
    const float* __restrict__ Wa, const float* __restrict__ ba,
    const float* __restrict__ Wf, const float* __restrict__ bf,
    float* __restrict__ out)
{
    __shared__ float Wsp_s[900], bsp_s[30], Wa_s[5760], ba_s[192], Wf_s[128], bf_s[4];
    __shared__ float ain[8][4][32];

    const int tid = threadIdx.x;
    for (int i = tid; i < 900; i += 256) Wsp_s[i] = Wsp[i];
    for (int i = tid; i < 5760; i += 256) Wa_s[i] = Wa[i];
    if (tid < 30)  bsp_s[tid] = bsp[tid];
    if (tid < 192) ba_s[tid]  = ba[tid];
    if (tid < 128) Wf_s[tid]  = Wf[tid];
    if (tid < 4)   bf_s[tid]  = bf[tid];
    __syncthreads();

    const int warp = tid >> 5, lane = tid & 31;
    const int b = blockIdx.x * 8 + warp;

    float fvs = 0.f, fps = 0.f, fvd = 0.f, fpd = 0.f, yv = 0.f;
    if (lane < 30) {
        fvs = g_fvs[b * 30 + lane];
        fps = g_fps[b * 30 + lane];
        fvd = g_fvd[b * 30 + lane];
        fpd = g_fpd[b * 30 + lane];
        yv  = g_y30[b * 30 + lane];
    }

    float h1 = (lane < 30) ? bsp_s[lane] : 0.f;
    float h2 = h1;
    for (int i = 0; i < 30; i++) {
        float av = __shfl_sync(0xffffffffu, fvs, i);
        float bv = __shfl_sync(0xffffffffu, fps, i);
        float wv = (lane < 30) ? Wsp_s[i * 30 + lane] : 0.f;
        h1 = fmaf(av, wv, h1);
        h2 = fmaf(bv, wv, h2);
    }

    const int   pr = pairs[b];
    const float pf = (float)pr;
    const float h12 = h1 + h2;
    float m1 = fmaxf(h12, fmaxf(h1, h2));
    float lse1 = m1 + logf(2.f * expf(h12 - m1) + expf(h1 - m1) + expf(h2 - m1));
    float m2 = fmaxf(0.f, fmaxf(h1, h2));
    float lse2 = m2 + logf(2.f * expf(0.f - m2) + expf(h1 - m2) + expf(h2 - m2));
    const float favg = pf * (lse1 - lse2) + (1.f - pf) * h2;

    if (lane < 30) {
        ain[warp][0][lane] = fpd;
        ain[warp][1][lane] = favg;
        ain[warp][2][lane] = yv;
        ain[warp][3][lane] = fvd;
    }
    __syncwarp();

    float r[4][6];
#pragma unroll
    for (int g = 0; g < 6; g++) {
        float s0 = ba_s[g * 32 + lane], s1 = s0, s2 = s0, s3 = s0;
        for (int i = 0; i < 30; i++) {
            const float wv = Wa_s[i * 192 + g * 32 + lane];
            s0 = fmaf(ain[warp][0][i], wv, s0);
            s1 = fmaf(ain[warp][1][i], wv, s1);
            s2 = fmaf(ain[warp][2][i], wv, s2);
            s3 = fmaf(ain[warp][3][i], wv, s3);
        }
        r[0][g] = s0; r[1][g] = s1; r[2][g] = s2; r[3][g] = s3;
    }

    const float qsum3 = r[0][0] + r[1][0] + r[2][0];
    const float qm = pf * 0.25f * (qsum3 + r[3][0]) + (1.f - pf) * (qsum3 * (1.f / 3.f));

    float lg[4][4];
#pragma unroll
    for (int n = 0; n < 4; n++) {
#pragma unroll
        for (int t = 0; t < 4; t++) {
            float p = r[t][2 + n] * qm;
#pragma unroll
            for (int off = 16; off; off >>= 1) p += __shfl_xor_sync(0xffffffffu, p, off);
            lg[n][t] = p * 0.17677669529663687f;
        }
    }

#pragma unroll
    for (int n = 0; n < 4; n++) {
        const float l0 = lg[n][0], l1 = lg[n][1], l2 = lg[n][2], l3 = lg[n][3];
        float m = fmaxf(fmaxf(l0, l1), l2);
        if (pr) m = fmaxf(m, l3);
        const float e0 = expf(l0 - m), e1 = expf(l1 - m), e2 = expf(l2 - m);
        const float e3 = pr ? expf(l3 - m) : 0.f;
        const float inv = 1.f / (e0 + e1 + e2 + e3);
        const float ff = (e0 * r[0][1] + e1 * r[1][1] + e2 * r[2][1] + e3 * r[3][1]) * inv;
        float p = ff * Wf_s[lane * 4 + n];
#pragma unroll
        for (int off = 16; off; off >>= 1) p += __shfl_xor_sync(0xffffffffu, p, off);
        if (lane == 0) out[b * 4 + n] = p + bf_s[n];
    }
}

// =======================================================================
extern "C" void kernel_launch(void* const* d_in, const int* in_sizes, int n_in,
                              void* d_out, int out_size)
{
    (void)in_sizes; (void)n_in; (void)out_size;
    const int*   pairs = (const int*)d_in[0];
    const float* S_V  = (const float*)d_in[1];
    const float* S_P  = (const float*)d_in[2];
    const float* S_P1 = (const float*)d_in[3];
    const float* Wc_v = (const float*)d_in[4];  const float* bc_v = (const float*)d_in[5];
    const float* Ws_v = (const float*)d_in[6];  const float* bs_v = (const float*)d_in[7];
    const float* Wd_v = (const float*)d_in[8];  const float* bd_v = (const float*)d_in[9];
    const float* Wc_p = (const float*)d_in[10]; const float* bc_p = (const float*)d_in[11];
    const float* Ws_p = (const float*)d_in[12]; const float* bs_p = (const float*)d_in[13];
    const float* Wd_p = (const float*)d_in[14]; const float* bd_p = (const float*)d_in[15];
    const float* Wsp  = (const float*)d_in[16]; const float* bsp  = (const float*)d_in[17];
    const float* W1   = (const float*)d_in[18]; const float* b1   = (const float*)d_in[19];
    const float* W2   = (const float*)d_in[20]; const float* b2   = (const float*)d_in[21];
    const float* Wa   = (const float*)d_in[22]; const float* ba   = (const float*)d_in[23];
    const float* Wf   = (const float*)d_in[24]; const float* bf   = (const float*)d_in[25];
    float* out = (float*)d_out;

    cudaFuncSetAttribute(phys_kernel, cudaFuncAttributeMaxDynamicSharedMemorySize,
                         PHYS_SMEM);
    cudaFuncSetAttribute(encode_kernel, cudaFuncAttributeMaxDynamicSharedMemorySize,
                         ENC_SMEM);

    prep_w2t<<<80, 256>>>(W2);
    encode_kernel<<<NB, 512, ENC_SMEM>>>(S_V, S_P,
                                         Wc_v, bc_v, Ws_v, bs_v, Wd_v, bd_v,
                                         Wc_p, bc_p, Ws_p, bs_p, Wd_p, bd_p);
    phys_kernel<<<NB, 512, PHYS_SMEM>>>(S_P1, W1, b1, b2);
    fuse_kernel<<<NB / 8, 256>>>(pairs, Wsp, bsp, Wa, ba, Wf, bf, out);
}

// round 13
// speedup vs baseline: 1.3357x; 1.3357x over previous
#include <cuda_runtime.h>
#include <cuda_bf16.h>
#include <math.h>
#include <stdint.h>

#define NB 4096
#define FEATN 30

// ---------------- scratch (static device globals; no allocation) ----------------
__device__ float g_fvs[NB * FEATN];
__device__ float g_fvd[NB * FEATN];
__device__ float g_fps[NB * FEATN];
__device__ float g_fpd[NB * FEATN];
__device__ float g_y30[NB * FEATN];
__device__ __align__(16) unsigned char g_w2t[10 * 4096];

// ---------------- f32x2 helpers ----------------
typedef unsigned long long ull_t;
__device__ __forceinline__ ull_t f2pack(float lo, float hi) {
    ull_t r; asm("mov.b64 %0, {%1,%2};" : "=l"(r) : "f"(lo), "f"(hi)); return r;
}
__device__ __forceinline__ ull_t f2dup(float v) { return f2pack(v, v); }
__device__ __forceinline__ void f2fma(ull_t& d, ull_t a, ull_t b) {
    asm("fma.rn.f32x2 %0, %1, %2, %0;" : "+l"(d) : "l"(a), "l"(b));
}
__device__ __forceinline__ void f2unpack(ull_t v, float& lo, float& hi) {
    asm("mov.b64 {%0,%1}, %2;" : "=f"(lo), "=f"(hi) : "l"(v));
}

// ---------------- warp-MMA helpers ----------------
__device__ __forceinline__ uint32_t smem_u32(const void* p) {
    uint32_t a;
    asm("{ .reg .u64 t; cvta.to.shared.u64 t, %1; cvt.u32.u64 %0, t; }" : "=r"(a) : "l"(p));
    return a;
}
__device__ __forceinline__ uint32_t sw128(uint32_t o) { return o ^ ((o >> 3) & 0x70); }

__device__ __forceinline__ void ldmx4(uint32_t* r, uint32_t addr) {
    asm volatile("ldmatrix.sync.aligned.m8n8.x4.shared.b16 {%0,%1,%2,%3}, [%4];"
                 : "=r"(r[0]), "=r"(r[1]), "=r"(r[2]), "=r"(r[3]) : "r"(addr));
}
__device__ __forceinline__ void ldmx2(uint32_t* r, uint32_t addr) {
    asm volatile("ldmatrix.sync.aligned.m8n8.x2.shared.b16 {%0,%1}, [%2];"
                 : "=r"(r[0]), "=r"(r[1]) : "r"(addr));
}
__device__ __forceinline__ void mma16816(float* d, const uint32_t* a, const uint32_t* b) {
    asm volatile("mma.sync.aligned.m16n8k16.row.col.f32.bf16.bf16.f32 "
                 "{%0,%1,%2,%3}, {%4,%5,%6,%7}, {%8,%9}, {%0,%1,%2,%3};"
                 : "+f"(d[0]), "+f"(d[1]), "+f"(d[2]), "+f"(d[3])
                 : "r"(a[0]), "r"(a[1]), "r"(a[2]), "r"(a[3]), "r"(b[0]), "r"(b[1]));
}

// =======================================================================
// Prep: bf16 hi/lo SW128 tile images of conv2 weights.
// =======================================================================
__global__ void prep_w2t(const float* __restrict__ W2) {
    int i = blockIdx.x * 256 + threadIdx.x;
    if (i < 20480) {
        int tile = i >> 11;
        int rem  = i & 2047;
        int n = rem >> 6, c = rem & 63;
        int half = tile / 5, k = tile % 5;
        float w = (n < 30) ? W2[n * 320 + c * 5 + k] : 0.f;
        __nv_bfloat16 wh = __float2bfloat16(w);
        __nv_bfloat16 val = half ? __float2bfloat16(w - __bfloat162float(wh)) : wh;
        *reinterpret_cast<__nv_bfloat16*>(
            g_w2t + tile * 4096 + sw128((uint32_t)(n * 128 + c * 2))) = val;
    }
}

// =======================================================================
// Encode kernel v2b: conv1d(3->64,K=3) as im2col GEMM via mma.sync.
// im2col row r = S[3r..3r+8] (natural order: col j = k*3+c), weights
// PERMUTED to match (Wc[o][c][k] -> col k*3+c).  32B row stride,
// one block per (sample, modality), 256 threads, ~72 KB smem, 3 CTAs/SM.
// =======================================================================
#define E2_XH    0u
#define E2_XL    32768u
#define E2_W     65536u        /* hi 2048 B, lo 2048 B */
#define E2_PART  69632u        /* 8 warps x 64 floats */
#define E2_BC    71680u        /* 64 floats */
#define E2_HSH   71936u        /* 64 floats */
#define ENC_SMEM 72192

__global__ __launch_bounds__(256, 3) void encode_kernel(
    const float* __restrict__ S_V, const float* __restrict__ S_P,
    const float* __restrict__ Wc_v, const float* __restrict__ bc_v,
    const float* __restrict__ Ws_v, const float* __restrict__ bs_v,
    const float* __restrict__ Wd_v, const float* __restrict__ bd_v,
    const float* __restrict__ Wc_p, const float* __restrict__ bc_p,
    const float* __restrict__ Ws_p, const float* __restrict__ bs_p,
    const float* __restrict__ Wd_p, const float* __restrict__ bd_p)
{
    extern __shared__ __align__(16) unsigned char smraw[];
    const uint32_t smb = smem_u32(smraw);

    const int tid  = threadIdx.x;
    const int b    = blockIdx.x;
    const int mo   = blockIdx.y;
    const int lane = tid & 31;
    const int wid  = tid >> 5;

    float* part = (float*)(smraw + E2_PART);
    float* bcs  = (float*)(smraw + E2_BC);
    float* hsh  = (float*)(smraw + E2_HSH);

    // ---- im2col fill: row r <- S[3r..3r+8], 9 bf16 + 7 zeros, hi/lo --------
    {
        const float* Sb = (mo ? S_P : S_V) + (size_t)b * 3072;
        for (int r = tid; r < 1024; r += 256) {
            uint4 h0 = make_uint4(0, 0, 0, 0), h1 = h0, l0 = h0, l1 = h0;
            if (r <= 1021) {
                float f[9];
#pragma unroll
                for (int i = 0; i < 9; i++) f[i] = Sb[3 * r + i];
                uint32_t hh[9], ll[9];
#pragma unroll
                for (int i = 0; i < 9; i++) {
                    __nv_bfloat16 vh = __float2bfloat16(f[i]);
                    __nv_bfloat16 vl = __float2bfloat16(f[i] - __bfloat162float(vh));
                    hh[i] = (uint32_t)*reinterpret_cast<uint16_t*>(&vh);
                    ll[i] = (uint32_t)*reinterpret_cast<uint16_t*>(&vl);
                }
                h0.x = hh[0] | (hh[1] << 16); h0.y = hh[2] | (hh[3] << 16);
                h0.z = hh[4] | (hh[5] << 16); h0.w = hh[6] | (hh[7] << 16);
                h1.x = hh[8];
                l0.x = ll[0] | (ll[1] << 16); l0.y = ll[2] | (ll[3] << 16);
                l0.z = ll[4] | (ll[5] << 16); l0.w = ll[6] | (ll[7] << 16);
                l1.x = ll[8];
            }
            *reinterpret_cast<uint4*>(smraw + E2_XH + r * 32)      = h0;
            *reinterpret_cast<uint4*>(smraw + E2_XH + r * 32 + 16) = h1;
            *reinterpret_cast<uint4*>(smraw + E2_XL + r * 32)      = l0;
            *reinterpret_cast<uint4*>(smraw + E2_XL + r * 32 + 16) = l1;
        }
    }
    // ---- weights: Wc[o][c][k] -> col jj = k*3+c (matches im2col order) -----
    {
        if (tid < 128) {
            const uint32_t base = E2_W + (uint32_t)(tid >> 6) * 2048u +
                                  (uint32_t)(tid & 63) * 32u;
            *reinterpret_cast<uint16_t*>(smraw + base + 18) = 0;
            *reinterpret_cast<uint32_t*>(smraw + base + 20) = 0;
            *reinterpret_cast<uint32_t*>(smraw + base + 24) = 0;
            *reinterpret_cast<uint32_t*>(smraw + base + 28) = 0;
        }
        const float* Wc = mo ? Wc_p : Wc_v;
        for (int i = tid; i < 576; i += 256) {
            const int o = i / 9, j = i - o * 9;
            const int c = j / 3, k = j - c * 3;
            const int jj = k * 3 + c;               // PERMUTED to k-major
            const float w = Wc[i];
            __nv_bfloat16 wh = __float2bfloat16(w);
            __nv_bfloat16 wl = __float2bfloat16(w - __bfloat162float(wh));
            *reinterpret_cast<__nv_bfloat16*>(smraw + E2_W + o * 32 + jj * 2) = wh;
            *reinterpret_cast<__nv_bfloat16*>(smraw + E2_W + 2048 + o * 32 + jj * 2) = wl;
        }
        if (tid < 64) bcs[tid] = (mo ? bc_p : bc_v)[tid];
    }
    __syncthreads();

    // ---- MMA phase: 8 m-tiles/warp, B fragments register-resident ----------
    uint32_t bhf[8][2], blf[8][2];
#pragma unroll
    for (int nt = 0; nt < 8; nt++) {
        const uint32_t baddr = smb + E2_W +
            (uint32_t)(nt * 8 + (lane & 7)) * 32 + (uint32_t)((lane >> 3) & 1) * 16;
        ldmx2(bhf[nt], baddr);
        ldmx2(blf[nt], baddr + 2048);
    }

    float s0[8], s1[8];
#pragma unroll
    for (int nt = 0; nt < 8; nt++) { s0[nt] = 0.f; s1[nt] = 0.f; }

#pragma unroll
    for (int mt = 0; mt < 8; mt++) {
        const int R = (wid * 8 + mt) * 16;
        const uint32_t ao = smb + E2_XH +
            (uint32_t)(R + (lane & 15)) * 32 + (uint32_t)(lane >> 4) * 16;
        uint32_t Ah[4], Al[4];
        ldmx4(Ah, ao);
        ldmx4(Al, ao + 32768u);
        const bool r1ok = (R + 8 + (lane >> 2)) < 1022;
#pragma unroll
        for (int nt = 0; nt < 8; nt++) {
            float d[4] = {0.f, 0.f, 0.f, 0.f};
            mma16816(d, Ah, bhf[nt]);
            mma16816(d, Al, bhf[nt]);
            mma16816(d, Ah, blf[nt]);
            const int o = nt * 8 + (lane & 3) * 2;
            const float bias0 = bcs[o], bias1 = bcs[o + 1];
            s0[nt] += fmaxf(d[0] + bias0, 0.f);
            s1[nt] += fmaxf(d[1] + bias1, 0.f);
            if (r1ok) {
                s0[nt] += fmaxf(d[2] + bias0, 0.f);
                s1[nt] += fmaxf(d[3] + bias1, 0.f);
            }
        }
    }

#pragma unroll
    for (int nt = 0; nt < 8; nt++) {
#pragma unroll
        for (int off = 4; off <= 16; off <<= 1) {
            s0[nt] += __shfl_xor_sync(0xffffffffu, s0[nt], off);
            s1[nt] += __shfl_xor_sync(0xffffffffu, s1[nt], off);
        }
    }
    if (lane < 4) {
#pragma unroll
        for (int nt = 0; nt < 8; nt++) {
            const int o = nt * 8 + lane * 2;
            part[wid * 64 + o]     = s0[nt];
            part[wid * 64 + o + 1] = s1[nt];
        }
    }
    __syncthreads();

    if (tid < 64) {
        float s = 0.f;
#pragma unroll
        for (int w = 0; w < 8; w++) s += part[w * 64 + tid];
        hsh[tid] = s * (1.f / 1022.f);
    }
    __syncthreads();

    if (tid < 60) {
        const int  j2 = tid % 30;
        const bool first = tid < 30;
        const float* Wm = first ? (mo ? Ws_p : Ws_v) : (mo ? Wd_p : Wd_v);
        const float* bm = first ? (mo ? bs_p : bs_v) : (mo ? bd_p : bd_v);
        float* outp = first ? (mo ? g_fps : g_fvs) : (mo ? g_fpd : g_fvd);
        float s = bm[j2];
        for (int i = 0; i < 64; i++) s = fmaf(hsh[i], Wm[i * 30 + j2], s);
        outp[b * 30 + j2] = s;
    }
}

// =======================================================================
// Physical-model kernel (unchanged from R10, 560us version).
// =======================================================================
#define XS_OFF      0u
#define WBUF_OFF    0u
#define CO_OFF      0u
#define P1H_OFF     40960u
#define P1L_OFF     73728u
#define PART_OFF    106496u
#define PHYS_SMEM   108416
#define COSTR       33

__global__ __launch_bounds__(512, 2) void phys_kernel(
    const float* __restrict__ S_P1,
    const float* __restrict__ W1, const float* __restrict__ b1,
    const float* __restrict__ b2)
{
    extern __shared__ __align__(16) unsigned char smraw[];
    const uint32_t smb = smem_u32(smraw);
    float* xs   = (float*)(smraw + XS_OFF);
    float* part = (float*)(smraw + PART_OFF);

    const int tid  = threadIdx.x;
    const int b    = blockIdx.x;
    const int wid  = tid >> 5;
    const int lane = tid & 31;

    const float* Sb = S_P1 + (size_t)b * 3072;
    for (int i = tid; i < 3072; i += 512) xs[(i % 3) * 1032 + i / 3] = Sb[i];
    __syncthreads();

    {
        const int pg = tid >> 4;
        const int tg = tid & 15;
        const int o0 = pg * 2;
        ull_t WU[15];
#pragma unroll
        for (int i = 0; i < 15; i++)
            WU[i] = f2pack(W1[o0 * 15 + i], W1[o0 * 15 + 15 + i]);
        const ull_t Bp = f2pack(b1[o0], b1[o0 + 1]);

        for (int m = 0; m < 16; m++) {
            const int j = tg + m * 16;
            if (j < 255) {
                const int t0 = 4 * j;
                ull_t A[4] = {Bp, Bp, Bp, Bp};
#pragma unroll
                for (int c = 0; c < 3; c++) {
                    const float* xr = xs + c * 1032 + t0;
                    float4 qa = *(const float4*)xr;
                    float4 qb = *(const float4*)(xr + 4);
                    ull_t X[8];
                    X[0] = f2dup(qa.x); X[1] = f2dup(qa.y); X[2] = f2dup(qa.z);
                    X[3] = f2dup(qa.w); X[4] = f2dup(qb.x); X[5] = f2dup(qb.y);
                    X[6] = f2dup(qb.z); X[7] = f2dup(qb.w);
#pragma unroll
                    for (int k = 0; k < 5; k++) {
                        const ull_t W = WU[c * 5 + k];
#pragma unroll
                        for (int p = 0; p < 4; p++) f2fma(A[p], X[p + k], W);
                    }
                }
                float u[4], v[4];
#pragma unroll
                for (int p = 0; p < 4; p++) f2unpack(A[p], u[p], v[p]);
                const float pa = fmaxf(fmaxf(u[0], u[1]), fmaxf(u[2], u[3]));
                const float pb = fmaxf(fmaxf(v[0], v[1]), fmaxf(v[2], v[3]));
                __nv_bfloat16 h0 = __float2bfloat16(pa);
                __nv_bfloat16 h1 = __float2bfloat16(pb);
                __nv_bfloat16 l0 = __float2bfloat16(pa - __bfloat162float(h0));
                __nv_bfloat16 l1 = __float2bfloat16(pb - __bfloat162float(h1));
                const uint32_t off = sw128((uint32_t)(j * 128 + o0 * 2));
                *reinterpret_cast<__nv_bfloat162*>(smraw + P1H_OFF + off) =
                    __halves2bfloat162(h0, h1);
                *reinterpret_cast<__nv_bfloat162*>(smraw + P1L_OFF + off) =
                    __halves2bfloat162(l0, l1);
            }
        }
    }
    if (tid < 32) {
        const uint32_t off = sw128((uint32_t)(255 * 128 + tid * 4));
        *reinterpret_cast<uint32_t*>(smraw + P1H_OFF + off) = 0u;
        *reinterpret_cast<uint32_t*>(smraw + P1L_OFF + off) = 0u;
    }
    __syncthreads();

    {
        const uint4* gw = (const uint4*)g_w2t;
        uint4* swp = (uint4*)(smraw + WBUF_OFF);
        for (int i = tid; i < 2560; i += 512) swp[i] = gw[i];
    }
    __syncthreads();

    const uint32_t a_rowl = (uint32_t)(lane & 15);
    const uint32_t a_koff = (uint32_t)((lane >> 4) * 16);
    const uint32_t bn     = (uint32_t)(lane & 7) * 128;
    const uint32_t bkoff  = (uint32_t)((lane >> 3) & 1) * 16;

    float d[4][4];
#pragma unroll
    for (int nt = 0; nt < 4; nt++)
#pragma unroll
        for (int i = 0; i < 4; i++) d[nt][i] = 0.f;

#pragma unroll
    for (int k = 0; k < 5; k++) {
        const uint32_t bbase_h = smb + WBUF_OFF + (uint32_t)k * 4096;
        const uint32_t bbase_l = bbase_h + 5u * 4096;
        const uint32_t arow    = (uint32_t)(wid * 16 + k) + a_rowl;
#pragma unroll
        for (int ks = 0; ks < 4; ks++) {
            uint32_t Ah[4], Al[4];
            const uint32_t ao = sw128(arow * 128 + (uint32_t)ks * 32 + a_koff);
            ldmx4(Ah, smb + P1H_OFF + ao);
            ldmx4(Al, smb + P1L_OFF + ao);
#pragma unroll
            for (int nt = 0; nt < 4; nt++) {
                const uint32_t bo =
                    sw128(bn + (uint32_t)nt * 1024 + (uint32_t)ks * 32 + bkoff);
                uint32_t bh[2], bl[2];
                ldmx2(bh, bbase_h + bo);
                ldmx2(bl, bbase_l + bo);
                mma16816(d[nt], Ah, bh);
                mma16816(d[nt], Al, bh);
                mma16816(d[nt], Ah, bl);
            }
        }
    }
    __syncthreads();

    {
        float* conv_out = (float*)(smraw + CO_OFF);
        const int t0 = wid * 16 + (lane >> 2);
        const int t1 = t0 + 8;
        const int n0 = (lane & 3) * 2;
#pragma unroll
        for (int nt = 0; nt < 4; nt++) {
            const int n = nt * 8 + n0;
            if (t0 < 248) {
                conv_out[t0 * COSTR + n]     = d[nt][0];
                conv_out[t0 * COSTR + n + 1] = d[nt][1];
            }
            if (t1 < 248) {
                conv_out[t1 * COSTR + n]     = d[nt][2];
                conv_out[t1 * COSTR + n + 1] = d[nt][3];
            }
        }
    }
    __syncthreads();

    {
        float* conv_out = (float*)(smraw + CO_OFF);
        if (tid < 480) {
            const int n = tid >> 4, jg = tid & 15;
            float s = 0.f;
#pragma unroll
            for (int j = jg; j < 62; j += 16) {
                const float* cr = conv_out + 4 * j * COSTR + n;
                float mx = fmaxf(fmaxf(cr[0], cr[COSTR]),
                                 fmaxf(cr[2 * COSTR], cr[3 * COSTR]));
                s += mx;
            }
            part[n * 16 + jg] = s;
        }
    }
    __syncthreads();
    if (tid < 30) {
        float s = 0.f;
#pragma unroll
        for (int g = 0; g < 16; g++) s += part[tid * 16 + g];
        g_y30[b * 30 + tid] = s * (1.f / 62.f) + b2[tid];
    }
}

// =======================================================================
// Fusion kernel (unchanged).
// =======================================================================
__global__ __launch_bounds__(256) void fuse_kernel(
    const int* __restrict__ pairs,
    const float* __restrict__ Wsp, const float* __restrict__ bsp,
    const float* __restrict__ Wa, const float* __restrict__ ba,
    const float* __restrict__ Wf, const float* __restrict__ bf,
    float* __restrict__ out)
{
    __shared__ float Wsp_s[900], bsp_s[30], Wa_s[5760], ba_s[192], Wf_s[128], bf_s[4];
    __shared__ float ain[8][4][32];

    const int tid = threadIdx.x;
    for (int i = tid; i < 900; i += 256) Wsp_s[i] = Wsp[i];
    for (int i = tid; i < 5760; i += 256) Wa_s[i] = Wa[i];
    if (tid < 30)  bsp_s[tid] = bsp[tid];
    if (tid < 192) ba_s[tid]  = ba[tid];
    if (tid < 128) Wf_s[tid]  = Wf[tid];
    if (tid < 4)   bf_s[tid]  = bf[tid];
    __syncthreads();

    const int warp = tid >> 5, lane = tid & 31;
    const int b = blockIdx.x * 8 + warp;

    float fvs = 0.f, fps = 0.f, fvd = 0.f, fpd = 0.f, yv = 0.f;
    if (lane < 30) {
        fvs = g_fvs[b * 30 + lane];
        fps = g_fps[b * 30 + lane];
        fvd = g_fvd[b * 30 + lane];
        fpd = g_fpd[b * 30 + lane];
        yv  = g_y30[b * 30 + lane];
    }

    float h1 = (lane < 30) ? bsp_s[lane] : 0.f;
    float h2 = h1;
    for (int i = 0; i < 30; i++) {
        float av = __shfl_sync(0xffffffffu, fvs, i);
        float bv = __shfl_sync(0xffffffffu, fps, i);
        float wv = (lane < 30) ? Wsp_s[i * 30 + lane] : 0.f;
        h1 = fmaf(av, wv, h1);
        h2 = fmaf(bv, wv, h2);
    }

    const int   pr = pairs[b];
    const float pf = (float)pr;
    const float h12 = h1 + h2;
    float m1 = fmaxf(h12, fmaxf(h1, h2));
    float lse1 = m1 + logf(2.f * expf(h12 - m1) + expf(h1 - m1) + expf(h2 - m1));
    float m2 = fmaxf(0.f, fmaxf(h1, h2));
    float lse2 = m2 + logf(2.f * expf(0.f - m2) + expf(h1 - m2) + expf(h2 - m2));
    const float favg = pf * (lse1 - lse2) + (1.f - pf) * h2;

    if (lane < 30) {
        ain[warp][0][lane] = fpd;
        ain[warp][1][lane] = favg;
        ain[warp][2][lane] = yv;
        ain[warp][3][lane] = fvd;
    }
    __syncwarp();

    float r[4][6];
#pragma unroll
    for (int g = 0; g < 6; g++) {
        float s0 = ba_s[g * 32 + lane], s1 = s0, s2 = s0, s3 = s0;
        for (int i = 0; i < 30; i++) {
            const float wv = Wa_s[i * 192 + g * 32 + lane];
            s0 = fmaf(ain[warp][0][i], wv, s0);
            s1 = fmaf(ain[warp][1][i], wv, s1);
            s2 = fmaf(ain[warp][2][i], wv, s2);
            s3 = fmaf(ain[warp][3][i], wv, s3);
        }
        r[0][g] = s0; r[1][g] = s1; r[2][g] = s2; r[3][g] = s3;
    }

    const float qsum3 = r[0][0] + r[1][0] + r[2][0];
    const float qm = pf * 0.25f * (qsum3 + r[3][0]) + (1.f - pf) * (qsum3 * (1.f / 3.f));

    float lg[4][4];
#pragma unroll
    for (int n = 0; n < 4; n++) {
#pragma unroll
        for (int t = 0; t < 4; t++) {
            float p = r[t][2 + n] * qm;
#pragma unroll
            for (int off = 16; off; off >>= 1) p += __shfl_xor_sync(0xffffffffu, p, off);
            lg[n][t] = p * 0.17677669529663687f;
        }
    }

#pragma unroll
    for (int n = 0; n < 4; n++) {
        const float l0 = lg[n][0], l1 = lg[n][1], l2 = lg[n][2], l3 = lg[n][3];
        float m = fmaxf(fmaxf(l0, l1), l2);
        if (pr) m = fmaxf(m, l3);
        const float e0 = expf(l0 - m), e1 = expf(l1 - m), e2 = expf(l2 - m);
        const float e3 = pr ? expf(l3 - m) : 0.f;
        const float inv = 1.f / (e0 + e1 + e2 + e3);
        const float ff = (e0 * r[0][1] + e1 * r[1][1] + e2 * r[2][1] + e3 * r[3][1]) * inv;
        float p = ff * Wf_s[lane * 4 + n];
#pragma unroll
        for (int off = 16; off; off >>= 1) p += __shfl_xor_sync(0xffffffffu, p, off);
        if (lane == 0) out[b * 4 + n] = p + bf_s[n];
    }
}

// =======================================================================
extern "C" void kernel_launch(void* const* d_in, const int* in_sizes, int n_in,
                              void* d_out, int out_size)
{
    (void)in_sizes; (void)n_in; (void)out_size;
    const int*   pairs = (const int*)d_in[0];
    const float* S_V  = (const float*)d_in[1];
    const float* S_P  = (const float*)d_in[2];
    const float* S_P1 = (const float*)d_in[3];
    const float* Wc_v = (const float*)d_in[4];  const float* bc_v = (const float*)d_in[5];
    const float* Ws_v = (const float*)d_in[6];  const float* bs_v = (const float*)d_in[7];
    const float* Wd_v = (const float*)d_in[8];  const float* bd_v = (const float*)d_in[9];
    const float* Wc_p = (const float*)d_in[10]; const float* bc_p = (const float*)d_in[11];
    const float* Ws_p = (const float*)d_in[12]; const float* bs_p = (const float*)d_in[13];
    const float* Wd_p = (const float*)d_in[14]; const float* bd_p = (const float*)d_in[15];
    const float* Wsp  = (const float*)d_in[16]; const float* bsp  = (const float*)d_in[17];
    const float* W1   = (const float*)d_in[18]; const float* b1   = (const float*)d_in[19];
    const float* W2   = (const float*)d_in[20]; const float* b2   = (const float*)d_in[21];
    const float* Wa   = (const float*)d_in[22]; const float* ba   = (const float*)d_in[23];
    const float* Wf   = (const float*)d_in[24]; const float* bf   = (const float*)d_in[25];
    float* out = (float*)d_out;

    cudaFuncSetAttribute(phys_kernel, cudaFuncAttributeMaxDynamicSharedMemorySize,
                         PHYS_SMEM);
    cudaFuncSetAttribute(encode_kernel, cudaFuncAttributeMaxDynamicSharedMemorySize,
                         ENC_SMEM);

    prep_w2t<<<80, 256>>>(W2);
    encode_kernel<<<dim3(NB, 2), 256, ENC_SMEM>>>(S_V, S_P,
                                        Wc_v, bc_v, Ws_v, bs_v, Wd_v, bd_v,
                                        Wc_p, bc_p, Ws_p, bs_p, Wd_p, bd_p);
    phys_kernel<<<NB, 512, PHYS_SMEM>>>(S_P1, W1, b1, b2);
    fuse_kernel<<<NB / 8, 256>>>(pairs, Wsp, bsp, Wa, ba, Wf, bf, out);
}